// round 2
// baseline (speedup 1.0000x reference)
#include <cuda_runtime.h>
#include <cstdint>

// Problem constants: B=2, H=16, S=2048, D=64, temperature=8
#define S_LEN 2048
#define D_DIM 64
#define TQ    16        // q rows per CTA
#define CK    256       // key chunk
#define NTHREADS 256

__device__ __forceinline__ unsigned long long pk2(float a, float b) {
    unsigned long long r;
    asm("mov.b64 %0, {%1, %2};" : "=l"(r) : "f"(a), "f"(b));
    return r;
}
__device__ __forceinline__ unsigned long long f2fma(unsigned long long a,
                                                    unsigned long long b,
                                                    unsigned long long c) {
    unsigned long long d;
    asm("fma.rn.f32x2 %0, %1, %2, %3;" : "=l"(d) : "l"(a), "l"(b), "l"(c));
    return d;
}
__device__ __forceinline__ float2 upk2(unsigned long long a) {
    float lo, hi;
    asm("mov.b64 {%0, %1}, %2;" : "=f"(lo), "=f"(hi) : "l"(a));
    return make_float2(lo, hi);
}

__global__ __launch_bounds__(NTHREADS, 1)
void sdpa_kernel(const float* __restrict__ q, const float* __restrict__ k,
                 const float* __restrict__ v, const int* __restrict__ mask,
                 float* __restrict__ outp, float* __restrict__ attnp)
{
    extern __shared__ float smem[];
    float* Sbuf  = smem;                          // [TQ][S_LEN]  = 128 KB (exp values)
    float* Kt    = Sbuf + TQ * S_LEN;             // [D][CK] swizzled (also reused as Vs[CK][D])
    float* Qst   = Kt + D_DIM * CK;               // [D][TQ] transposed q
    float* Zs    = Qst + D_DIM * TQ;              // [TQ]
    float* invZs = Zs + TQ;                       // [TQ]

    const int tid = threadIdx.x;
    const int qt  = blockIdx.x;                   // 0..127 q-tile
    const int bh  = blockIdx.y;                   // 0..31  (b*16+h)
    const int b   = bh >> 4;
    const int q0  = qt * TQ;

    const float* qb = q + (size_t)bh * S_LEN * D_DIM;
    const float* kb = k + (size_t)bh * S_LEN * D_DIM;
    const float* vb = v + (size_t)bh * S_LEN * D_DIM;
    const int*   mb = mask + (size_t)b * S_LEN * S_LEN;

    // ---- load Q transposed: Qst[d][r]  (FIX: grid-stride over all TQ*D elems) ----
    #pragma unroll
    for (int idx = tid; idx < TQ * D_DIM; idx += NTHREADS) {
        int r = idx / D_DIM, d = idx % D_DIM;
        Qst[d * TQ + r] = qb[(size_t)(q0 + r) * D_DIM + d];
    }
    if (tid < TQ) Zs[tid] = 0.f;

    // ---- phase 1: QK^T + mask + exp -> Sbuf, partial Z in regs ----
    const int ty = tid >> 6;          // 0..3   (4 q rows each)
    const int tx = tid & 63;          // 0..63  (4 keys each per chunk)
    const int colbase = tx << 2;

    float zp[4] = {0.f, 0.f, 0.f, 0.f};

    for (int kbase = 0; kbase < S_LEN; kbase += CK) {
        __syncthreads();
        // load K chunk transposed with XOR swizzle: element (d,key) -> Kt[d*CK + (key ^ (d&60))]
        {
            const float4* kg4 = (const float4*)(kb + (size_t)kbase * D_DIM);
            #pragma unroll
            for (int t = 0; t < (CK * D_DIM / 4) / NTHREADS; ++t) {
                int idx = tid + t * NTHREADS;
                int key = idx >> 4, dg = idx & 15;
                float4 val = kg4[idx];
                int col = key ^ (dg << 2);
                Kt[(dg * 4 + 0) * CK + col] = val.x;
                Kt[(dg * 4 + 1) * CK + col] = val.y;
                Kt[(dg * 4 + 2) * CK + col] = val.z;
                Kt[(dg * 4 + 3) * CK + col] = val.w;
            }
        }
        __syncthreads();

        unsigned long long acc[4][2];
        #pragma unroll
        for (int i = 0; i < 4; ++i) { acc[i][0] = 0ull; acc[i][1] = 0ull; }

        #pragma unroll 8
        for (int d = 0; d < D_DIM; ++d) {
            int col = colbase ^ (d & 60);
            float4 kv = *(const float4*)&Kt[d * CK + col];
            unsigned long long k01 = pk2(kv.x, kv.y);
            unsigned long long k23 = pk2(kv.z, kv.w);
            float4 qv = *(const float4*)&Qst[d * TQ + (ty << 2)];
            unsigned long long qq;
            qq = pk2(qv.x, qv.x); acc[0][0] = f2fma(qq, k01, acc[0][0]); acc[0][1] = f2fma(qq, k23, acc[0][1]);
            qq = pk2(qv.y, qv.y); acc[1][0] = f2fma(qq, k01, acc[1][0]); acc[1][1] = f2fma(qq, k23, acc[1][1]);
            qq = pk2(qv.z, qv.z); acc[2][0] = f2fma(qq, k01, acc[2][0]); acc[2][1] = f2fma(qq, k23, acc[2][1]);
            qq = pk2(qv.w, qv.w); acc[3][0] = f2fma(qq, k01, acc[3][0]); acc[3][1] = f2fma(qq, k23, acc[3][1]);
        }

        // epilogue: mask + exp, write to Sbuf
        #pragma unroll
        for (int i = 0; i < 4; ++i) {
            int r = (ty << 2) + i;
            int gq = q0 + r;
            float2 a0 = upk2(acc[i][0]);
            float2 a1 = upk2(acc[i][1]);
            const int4 m = *(const int4*)(mb + (size_t)gq * S_LEN + kbase + colbase);
            float e0 = m.x ? __expf(a0.x * 0.125f) : 0.f;
            float e1 = m.y ? __expf(a0.y * 0.125f) : 0.f;
            float e2 = m.z ? __expf(a1.x * 0.125f) : 0.f;
            float e3 = m.w ? __expf(a1.y * 0.125f) : 0.f;
            zp[i] += (e0 + e1) + (e2 + e3);
            *(float4*)&Sbuf[r * S_LEN + kbase + colbase] = make_float4(e0, e1, e2, e3);
        }
    }

    // ---- Z reduction ----
    #pragma unroll
    for (int i = 0; i < 4; ++i) atomicAdd(&Zs[(ty << 2) + i], zp[i]);
    __syncthreads();
    if (tid < TQ) {
        float z = Zs[tid];
        invZs[tid] = (z > 0.f) ? (1.0f / z) : 0.f;
    }
    __syncthreads();

    // ---- phase 3: write normalized attn (coalesced float4) ----
    {
        float* attnb = attnp + (size_t)bh * S_LEN * S_LEN;
        #pragma unroll 1
        for (int r = 0; r < TQ; ++r) {
            float iz = invZs[r];
            float4* dst = (float4*)(attnb + (size_t)(q0 + r) * S_LEN);
            const float4* src = (const float4*)(Sbuf + r * S_LEN);
            #pragma unroll
            for (int c = tid; c < S_LEN / 4; c += NTHREADS) {
                float4 e = src[c];
                dst[c] = make_float4(e.x * iz, e.y * iz, e.z * iz, e.w * iz);
            }
        }
    }

    // ---- phase 4: PV (out[r][d] = sum_k e[r][k] * v[k][d]) ----
    const int tp  = tid & 31;          // dim pair: dims {2tp, 2tp+1}
    const int tg4 = (tid >> 5) & 3;    // rows tg4*4 .. tg4*4+3
    const int kk  = tid >> 7;          // key-parity split (4-key groups)

    unsigned long long oacc[4] = {0ull, 0ull, 0ull, 0ull};
    float* Vs = Kt;  // reuse K smem as Vs[CK][D]

    for (int kbase = 0; kbase < S_LEN; kbase += CK) {
        __syncthreads();
        {
            const float4* vg4 = (const float4*)(vb + (size_t)kbase * D_DIM);
            float4* Vs4 = (float4*)Vs;
            #pragma unroll
            for (int t = 0; t < (CK * D_DIM / 4) / NTHREADS; ++t)
                Vs4[tid + t * NTHREADS] = vg4[tid + t * NTHREADS];
        }
        __syncthreads();

        for (int kb0 = kk * 4; kb0 < CK; kb0 += 8) {
            float pf[4][4];
            #pragma unroll
            for (int i = 0; i < 4; ++i) {
                float4 p = *(const float4*)&Sbuf[((tg4 << 2) + i) * S_LEN + kbase + kb0];
                pf[i][0] = p.x; pf[i][1] = p.y; pf[i][2] = p.z; pf[i][3] = p.w;
            }
            #pragma unroll
            for (int m = 0; m < 4; ++m) {
                unsigned long long v2 =
                    *(const unsigned long long*)&Vs[(kb0 + m) * D_DIM + (tp << 1)];
                #pragma unroll
                for (int i = 0; i < 4; ++i)
                    oacc[i] = f2fma(pk2(pf[i][m], pf[i][m]), v2, oacc[i]);
            }
        }
    }

    // ---- combine the two key-parity halves and write output ----
    __syncthreads();
    float* scratch = Qst;   // 1024 floats, Q no longer needed
    if (kk == 1) {
        #pragma unroll
        for (int i = 0; i < 4; ++i) {
            float2 f = upk2(oacc[i]);
            int r = (tg4 << 2) + i;
            scratch[r * D_DIM + (tp << 1)]     = f.x;
            scratch[r * D_DIM + (tp << 1) + 1] = f.y;
        }
    }
    __syncthreads();
    if (kk == 0) {
        #pragma unroll
        for (int i = 0; i < 4; ++i) {
            float2 f = upk2(oacc[i]);
            int r = (tg4 << 2) + i;
            float iz = invZs[r];
            float2 o;
            o.x = (f.x + scratch[r * D_DIM + (tp << 1)])     * iz;
            o.y = (f.y + scratch[r * D_DIM + (tp << 1) + 1]) * iz;
            *(float2*)&outp[((size_t)bh * S_LEN + q0 + r) * D_DIM + (tp << 1)] = o;
        }
    }
}

extern "C" void kernel_launch(void* const* d_in, const int* in_sizes, int n_in,
                              void* d_out, int out_size)
{
    const float* q    = (const float*)d_in[0];
    const float* k    = (const float*)d_in[1];
    const float* v    = (const float*)d_in[2];
    const int*   mask = (const int*)d_in[3];

    float* outp  = (float*)d_out;
    float* attnp = outp + (size_t)2 * 16 * 2048 * 64;   // output first, then attn

    size_t smem_bytes = (size_t)(TQ * S_LEN + D_DIM * CK + D_DIM * TQ + 2 * TQ) * sizeof(float);
    cudaFuncSetAttribute(sdpa_kernel, cudaFuncAttributeMaxDynamicSharedMemorySize,
                         (int)smem_bytes);

    dim3 grid(S_LEN / TQ, 2 * 16);   // (128 q-tiles, 32 bh)
    sdpa_kernel<<<grid, NTHREADS, smem_bytes>>>(q, k, v, mask, outp, attnp);
}